// round 4
// baseline (speedup 1.0000x reference)
#include <cuda_runtime.h>
#include <cuda_bf16.h>
#include <math.h>

// HardTripletLoss: fused pairwise-distance (Gram-matrix SGEMM) + hardest pos/neg
// selection + mean. B=4096, D=512, 64 classes, margin=0.5.

#define B_SZ 4096
#define D_SZ 512
#define BM 128
#define BN 128
#define BK 32
#define MARGIN_F 0.5f

// Scratch (device globals: no allocation allowed in kernel_launch)
__device__ float g_norms[B_SZ];
__device__ int   g_hp_bits[B_SZ];   // hardest positive, float bits (init -inf)
__device__ int   g_hn_bits[B_SZ];   // hardest negative, float bits (init +inf)
__device__ int   g_labels[B_SZ];    // normalized labels (int)
__device__ int   g_is64;            // label dtype flag

// ---------------------------------------------------------------------------
// Detect whether labels buffer is int64 or int32. int32 data reinterpreted as
// int64 packs two labels per word -> value >= 2^32 whenever the high label is
// nonzero (prob ~1 over 16 samples, labels uniform in [0,64)).
__global__ void detect_kernel(const long long* __restrict__ lab64) {
    if (threadIdx.x == 0) {
        int ok = 1;
        #pragma unroll
        for (int k = 0; k < 16; k++) {
            long long v = lab64[k];
            if (v < 0 || v >= (1LL << 31)) ok = 0;
        }
        g_is64 = ok;
    }
}

__global__ void convert_labels_kernel(const void* __restrict__ labp) {
    int i = blockIdx.x * blockDim.x + threadIdx.x;
    if (i < B_SZ) {
        if (g_is64) g_labels[i] = (int)((const long long*)labp)[i];
        else        g_labels[i] = ((const int*)labp)[i];
    }
}

// ---------------------------------------------------------------------------
// Row squared norms + re-init hp/hn scratch (every launch: deterministic).
__global__ void prep_kernel(const float* __restrict__ X) {
    int w    = blockIdx.x * (blockDim.x >> 5) + (threadIdx.x >> 5);
    int lane = threadIdx.x & 31;
    if (w >= B_SZ) return;
    const float* row = X + (size_t)w * D_SZ;
    float s = 0.f;
    #pragma unroll
    for (int k = lane; k < D_SZ; k += 32) {
        float v = row[k];
        s = fmaf(v, v, s);
    }
    #pragma unroll
    for (int m = 16; m >= 1; m >>= 1)
        s += __shfl_down_sync(0xffffffffu, s, m);
    if (lane == 0) {
        g_norms[w]   = s;
        g_hp_bits[w] = (int)0xFF800000;  // -inf
        g_hn_bits[w] = 0x7F800000;       // +inf
    }
}

// ---------------------------------------------------------------------------
// Fused 128x128 Gram tile + distance + hardest pos/neg epilogue.
// 256 threads, 8x8 register tile per thread, BK=32 smem staging.
__global__ __launch_bounds__(256, 2) void tile_kernel(const float* __restrict__ X) {
    __shared__ float As[BK][BM];
    __shared__ float Bs[BK][BN];
    __shared__ int   labB[BN];

    const int rowBase = blockIdx.y * BM;
    const int colBase = blockIdx.x * BN;
    const int tid = threadIdx.x;
    const int tx = tid & 15;   // col group (8 cols)
    const int ty = tid >> 4;   // row group (8 rows)

    if (tid < BN) labB[tid] = g_labels[colBase + tid];

    float acc[8][8];
    #pragma unroll
    for (int i = 0; i < 8; i++)
        #pragma unroll
        for (int j = 0; j < 8; j++) acc[i][j] = 0.f;

    for (int k0 = 0; k0 < D_SZ; k0 += BK) {
        __syncthreads();  // protect As/Bs from previous iteration's readers (and labB on iter 0)
        #pragma unroll
        for (int i = 0; i < 4; i++) {
            int l  = i * 256 + tid;
            int r  = l >> 3;          // row within tile (0..127)
            int kc = (l & 7) << 2;    // k offset within chunk (0,4,..,28)
            float4 va = *(const float4*)(X + (size_t)(rowBase + r) * D_SZ + k0 + kc);
            As[kc + 0][r] = va.x; As[kc + 1][r] = va.y;
            As[kc + 2][r] = va.z; As[kc + 3][r] = va.w;
            float4 vb = *(const float4*)(X + (size_t)(colBase + r) * D_SZ + k0 + kc);
            Bs[kc + 0][r] = vb.x; Bs[kc + 1][r] = vb.y;
            Bs[kc + 2][r] = vb.z; Bs[kc + 3][r] = vb.w;
        }
        __syncthreads();
        #pragma unroll
        for (int k = 0; k < BK; k++) {
            float a[8], b[8];
            *(float4*)(a)     = *(const float4*)(&As[k][ty * 8]);
            *(float4*)(a + 4) = *(const float4*)(&As[k][ty * 8 + 4]);
            *(float4*)(b)     = *(const float4*)(&Bs[k][tx * 8]);
            *(float4*)(b + 4) = *(const float4*)(&Bs[k][tx * 8 + 4]);
            #pragma unroll
            for (int i = 0; i < 8; i++)
                #pragma unroll
                for (int j = 0; j < 8; j++)
                    acc[i][j] = fmaf(a[i], b[j], acc[i][j]);
        }
    }

    // ---- epilogue: distances + hardest pos/neg per row ----
    const float NEG_INF = __int_as_float(0xFF800000);
    const float POS_INF = __int_as_float(0x7F800000);

    int   la[8];
    float na[8];
    #pragma unroll
    for (int i = 0; i < 8; i++) {
        int gi = rowBase + ty * 8 + i;
        la[i] = g_labels[gi];
        na[i] = g_norms[gi];
    }

    float hp[8], hn[8];
    #pragma unroll
    for (int i = 0; i < 8; i++) { hp[i] = NEG_INF; hn[i] = POS_INF; }

    #pragma unroll
    for (int j = 0; j < 8; j++) {
        int gj   = colBase + tx * 8 + j;
        float nb = g_norms[gj];
        int   lb = labB[tx * 8 + j];
        #pragma unroll
        for (int i = 0; i < 8; i++) {
            int gi = rowBase + ty * 8 + i;
            float sq = fmaxf(fmaf(-2.f, acc[i][j], na[i] + nb), 0.f);
            float d  = sqrtf(sq);
            if (la[i] == lb) {
                if (gi != gj) hp[i] = fmaxf(hp[i], d);   // exclude diagonal
            } else {
                hn[i] = fminf(hn[i], d);
            }
        }
    }

    // reduce across the 16 tx threads sharing the same 8 rows.
    // lane = (ty&1)*16 + tx -> xor over low 4 bits stays within the tx group.
    #pragma unroll
    for (int m = 8; m >= 1; m >>= 1) {
        #pragma unroll
        for (int i = 0; i < 8; i++) {
            hp[i] = fmaxf(hp[i], __shfl_xor_sync(0xffffffffu, hp[i], m));
            hn[i] = fminf(hn[i], __shfl_xor_sync(0xffffffffu, hn[i], m));
        }
    }

    if (tx == 0) {
        #pragma unroll
        for (int i = 0; i < 8; i++) {
            int gi = rowBase + ty * 8 + i;
            // distances are >= 0 -> float bits monotone as signed int.
            // -inf/+inf sentinels are no-ops against the init values.
            atomicMax(&g_hp_bits[gi], __float_as_int(hp[i]));
            atomicMin(&g_hn_bits[gi], __float_as_int(hn[i]));
        }
    }
}

// ---------------------------------------------------------------------------
__global__ void finalize_kernel(float* __restrict__ out) {
    __shared__ float ssum[1024];
    __shared__ int   scnt[1024];
    int t = threadIdx.x;
    float sum = 0.f;
    int cnt = 0;
    for (int i = t; i < B_SZ; i += 1024) {
        int hpb = g_hp_bits[i];
        int hnb = g_hn_bits[i];
        bool valid = (hpb != (int)0xFF800000) && (hnb != 0x7F800000);
        if (valid) {
            float hp = __int_as_float(hpb);
            float hn = __int_as_float(hnb);
            sum += fmaxf(hp - hn + MARGIN_F, 0.f);
            cnt += 1;
        }
    }
    ssum[t] = sum;
    scnt[t] = cnt;
    __syncthreads();
    for (int s = 512; s >= 1; s >>= 1) {
        if (t < s) {
            ssum[t] += ssum[t + s];
            scnt[t] += scnt[t + s];
        }
        __syncthreads();
    }
    if (t == 0) {
        out[0] = (scnt[0] > 0) ? (ssum[0] / (float)scnt[0]) : 0.f;
    }
}

// ---------------------------------------------------------------------------
extern "C" void kernel_launch(void* const* d_in, const int* in_sizes, int n_in,
                              void* d_out, int out_size) {
    const float* X    = (const float*)d_in[0];
    const void*  labp = d_in[1];
    float*       out  = (float*)d_out;

    detect_kernel<<<1, 32>>>((const long long*)labp);
    convert_labels_kernel<<<(B_SZ + 255) / 256, 256>>>(labp);
    prep_kernel<<<B_SZ / 8, 256>>>(X);

    dim3 grid(B_SZ / BN, B_SZ / BM);
    tile_kernel<<<grid, 256>>>(X);

    finalize_kernel<<<1, 1024>>>(out);
}

// round 6
// speedup vs baseline: 1.6902x; 1.6902x over previous
#include <cuda_runtime.h>
#include <cuda_bf16.h>
#include <math.h>

// HardTripletLoss: fused pairwise-distance (Gram-matrix SGEMM) + hardest pos/neg
// selection + mean. B=4096, D=512, 64 classes, margin=0.5.
// R4: exploit symmetry of the distance matrix — compute only block tiles with
// bx >= by (528 of 1024), each off-diagonal tile updates BOTH row and column
// hardest-pos/neg stats. ~1.9x less FFMA/LDS work.

#define B_SZ 4096
#define D_SZ 512
#define BM 128
#define BN 128
#define BK 32
#define NB (B_SZ / BM)              /* 32 block-rows */
#define NTILES (NB * (NB + 1) / 2)  /* 528 upper-triangular tiles */
#define MARGIN_F 0.5f

// Scratch (device globals: no allocation allowed in kernel_launch)
__device__ float g_norms[B_SZ];
__device__ int   g_hp_bits[B_SZ];   // hardest positive, float bits (init -inf)
__device__ int   g_hn_bits[B_SZ];   // hardest negative, float bits (init +inf)
__device__ int   g_labels[B_SZ];    // normalized labels (int)
__device__ int   g_is64;            // label dtype flag

// ---------------------------------------------------------------------------
// Detect whether labels buffer is int64 or int32. int32 data reinterpreted as
// int64 packs two labels per word -> value >= 2^32 whenever the high label is
// nonzero (prob ~1 over 16 samples, labels uniform in [0,64)).
__global__ void detect_kernel(const long long* __restrict__ lab64) {
    if (threadIdx.x == 0) {
        int ok = 1;
        #pragma unroll
        for (int k = 0; k < 16; k++) {
            long long v = lab64[k];
            if (v < 0 || v >= (1LL << 31)) ok = 0;
        }
        g_is64 = ok;
    }
}

__global__ void convert_labels_kernel(const void* __restrict__ labp) {
    int i = blockIdx.x * blockDim.x + threadIdx.x;
    if (i < B_SZ) {
        if (g_is64) g_labels[i] = (int)((const long long*)labp)[i];
        else        g_labels[i] = ((const int*)labp)[i];
    }
}

// ---------------------------------------------------------------------------
// Row squared norms + re-init hp/hn scratch (every launch: deterministic).
__global__ void prep_kernel(const float* __restrict__ X) {
    int w    = blockIdx.x * (blockDim.x >> 5) + (threadIdx.x >> 5);
    int lane = threadIdx.x & 31;
    if (w >= B_SZ) return;
    const float* row = X + (size_t)w * D_SZ;
    float s = 0.f;
    #pragma unroll
    for (int k = lane; k < D_SZ; k += 32) {
        float v = row[k];
        s = fmaf(v, v, s);
    }
    #pragma unroll
    for (int m = 16; m >= 1; m >>= 1)
        s += __shfl_down_sync(0xffffffffu, s, m);
    if (lane == 0) {
        g_norms[w]   = s;
        g_hp_bits[w] = (int)0xFF800000;  // -inf
        g_hn_bits[w] = 0x7F800000;       // +inf
    }
}

// ---------------------------------------------------------------------------
// Fused 128x128 Gram tile + distance + hardest pos/neg epilogue.
// 256 threads, 8x8 register tile per thread, BK=32 smem staging.
// Only upper-triangular block tiles (bx >= by); off-diagonal tiles update
// column stats too (symmetry).
__global__ __launch_bounds__(256, 2) void tile_kernel(const float* __restrict__ X) {
    __shared__ float As[BK][BM];
    __shared__ float Bs[BK][BN];
    __shared__ int   labB[BN];
    __shared__ int   colHp[BN];
    __shared__ int   colHn[BN];

    // ---- decode triangular tile index: t -> (by, bx), bx >= by ----
    const int t = blockIdx.x;
    float ff = (float)(2 * NB + 1);
    int by = (int)((ff - sqrtf(ff * ff - 8.0f * (float)t)) * 0.5f);
    if (by < 0) by = 0;
    if (by > NB - 1) by = NB - 1;
    // start(r) = r*NB - r*(r-1)/2 ; fix up float rounding
    while (by > 0 && (by * NB - by * (by - 1) / 2) > t) by--;
    while (((by + 1) * NB - (by + 1) * by / 2) <= t) by++;
    const int bx = by + (t - (by * NB - by * (by - 1) / 2));
    const bool diag = (bx == by);

    const int rowBase = by * BM;
    const int colBase = bx * BN;
    const int tid = threadIdx.x;
    const int tx = tid & 15;   // col group (8 cols)
    const int ty = tid >> 4;   // row group (8 rows)

    if (tid < BN) {
        labB[tid]  = g_labels[colBase + tid];
        colHp[tid] = (int)0xFF800000;  // -inf
        colHn[tid] = 0x7F800000;       // +inf
    }

    float acc[8][8];
    #pragma unroll
    for (int i = 0; i < 8; i++)
        #pragma unroll
        for (int j = 0; j < 8; j++) acc[i][j] = 0.f;

    for (int k0 = 0; k0 < D_SZ; k0 += BK) {
        __syncthreads();  // protect As/Bs from previous readers (and labB/colHp on iter 0)
        #pragma unroll
        for (int i = 0; i < 4; i++) {
            int l  = i * 256 + tid;
            int r  = l >> 3;          // row within tile (0..127)
            int kc = (l & 7) << 2;    // k offset within chunk (0,4,..,28)
            float4 va = *(const float4*)(X + (size_t)(rowBase + r) * D_SZ + k0 + kc);
            As[kc + 0][r] = va.x; As[kc + 1][r] = va.y;
            As[kc + 2][r] = va.z; As[kc + 3][r] = va.w;
            float4 vb = *(const float4*)(X + (size_t)(colBase + r) * D_SZ + k0 + kc);
            Bs[kc + 0][r] = vb.x; Bs[kc + 1][r] = vb.y;
            Bs[kc + 2][r] = vb.z; Bs[kc + 3][r] = vb.w;
        }
        __syncthreads();
        #pragma unroll
        for (int k = 0; k < BK; k++) {
            float a[8], b[8];
            *(float4*)(a)     = *(const float4*)(&As[k][ty * 8]);
            *(float4*)(a + 4) = *(const float4*)(&As[k][ty * 8 + 4]);
            *(float4*)(b)     = *(const float4*)(&Bs[k][tx * 8]);
            *(float4*)(b + 4) = *(const float4*)(&Bs[k][tx * 8 + 4]);
            #pragma unroll
            for (int i = 0; i < 8; i++)
                #pragma unroll
                for (int j = 0; j < 8; j++)
                    acc[i][j] = fmaf(a[i], b[j], acc[i][j]);
        }
    }

    // ---- epilogue: distances + hardest pos/neg (rows AND columns) ----
    const float NEG_INF = __int_as_float(0xFF800000);
    const float POS_INF = __int_as_float(0x7F800000);

    int   la[8];
    float na[8];
    #pragma unroll
    for (int i = 0; i < 8; i++) {
        int gi = rowBase + ty * 8 + i;
        la[i] = g_labels[gi];
        na[i] = g_norms[gi];
    }

    float hp[8], hn[8];
    #pragma unroll
    for (int i = 0; i < 8; i++) { hp[i] = NEG_INF; hn[i] = POS_INF; }

    #pragma unroll
    for (int j = 0; j < 8; j++) {
        int   cj = tx * 8 + j;
        int   gj = colBase + cj;
        float nb = g_norms[gj];
        int   lb = labB[cj];
        float hpc = NEG_INF, hnc = POS_INF;  // column-j partial over this thread's 8 rows
        #pragma unroll
        for (int i = 0; i < 8; i++) {
            int gi = rowBase + ty * 8 + i;
            float sq = fmaxf(fmaf(-2.f, acc[i][j], na[i] + nb), 0.f);
            float d  = sqrtf(sq);
            if (la[i] == lb) {
                if (gi != gj) {          // diagonal exclusion (only possible on diag tiles)
                    hp[i] = fmaxf(hp[i], d);
                    hpc   = fmaxf(hpc, d);
                }
            } else {
                hn[i] = fminf(hn[i], d);
                hnc   = fminf(hnc, d);
            }
        }
        if (!diag) {
            // combine the two ty values sharing this warp (lanes l and l+16)
            hpc = fmaxf(hpc, __shfl_xor_sync(0xffffffffu, hpc, 16));
            hnc = fminf(hnc, __shfl_xor_sync(0xffffffffu, hnc, 16));
            if ((tid & 16) == 0) {
                atomicMax(&colHp[cj], __float_as_int(hpc));
                atomicMin(&colHn[cj], __float_as_int(hnc));
            }
        }
    }

    // reduce row stats across the 16 tx threads sharing the same 8 rows.
    #pragma unroll
    for (int m = 8; m >= 1; m >>= 1) {
        #pragma unroll
        for (int i = 0; i < 8; i++) {
            hp[i] = fmaxf(hp[i], __shfl_xor_sync(0xffffffffu, hp[i], m));
            hn[i] = fminf(hn[i], __shfl_xor_sync(0xffffffffu, hn[i], m));
        }
    }

    if (tx == 0) {
        #pragma unroll
        for (int i = 0; i < 8; i++) {
            int gi = rowBase + ty * 8 + i;
            // distances are >= 0 -> float bits monotone as signed int.
            // -inf/+inf sentinels are no-ops against the init values.
            atomicMax(&g_hp_bits[gi], __float_as_int(hp[i]));
            atomicMin(&g_hn_bits[gi], __float_as_int(hn[i]));
        }
    }

    // flush column stats to global (off-diagonal tiles only; diag tile's
    // column pass is redundant with its row pass by symmetry)
    if (!diag) {
        __syncthreads();
        if (tid < BN) {
            atomicMax(&g_hp_bits[colBase + tid], colHp[tid]);
            atomicMin(&g_hn_bits[colBase + tid], colHn[tid]);
        }
    }
}

// ---------------------------------------------------------------------------
__global__ void finalize_kernel(float* __restrict__ out) {
    __shared__ float ssum[1024];
    __shared__ int   scnt[1024];
    int t = threadIdx.x;
    float sum = 0.f;
    int cnt = 0;
    for (int i = t; i < B_SZ; i += 1024) {
        int hpb = g_hp_bits[i];
        int hnb = g_hn_bits[i];
        bool valid = (hpb != (int)0xFF800000) && (hnb != 0x7F800000);
        if (valid) {
            float hp = __int_as_float(hpb);
            float hn = __int_as_float(hnb);
            sum += fmaxf(hp - hn + MARGIN_F, 0.f);
            cnt += 1;
        }
    }
    ssum[t] = sum;
    scnt[t] = cnt;
    __syncthreads();
    for (int s = 512; s >= 1; s >>= 1) {
        if (t < s) {
            ssum[t] += ssum[t + s];
            scnt[t] += scnt[t + s];
        }
        __syncthreads();
    }
    if (t == 0) {
        out[0] = (scnt[0] > 0) ? (ssum[0] / (float)scnt[0]) : 0.f;
    }
}

// ---------------------------------------------------------------------------
extern "C" void kernel_launch(void* const* d_in, const int* in_sizes, int n_in,
                              void* d_out, int out_size) {
    const float* X    = (const float*)d_in[0];
    const void*  labp = d_in[1];
    float*       out  = (float*)d_out;

    detect_kernel<<<1, 32>>>((const long long*)labp);
    convert_labels_kernel<<<(B_SZ + 255) / 256, 256>>>(labp);
    prep_kernel<<<B_SZ / 8, 256>>>(X);

    tile_kernel<<<NTILES, 256>>>(X);

    finalize_kernel<<<1, 1024>>>(out);
}

// round 9
// speedup vs baseline: 4.5706x; 2.7041x over previous
#include <cuda_runtime.h>
#include <cuda_bf16.h>
#include <math.h>
#include <stdint.h>

// HardTripletLoss on GB300 (base sm_103 target): HMMA (mma.sync bf16) Gram GEMM
// + fused hardest pos/neg. B=4096, D=512, 64 classes, margin=0.5.
// R7: tcgen05 is unavailable (harness targets sm_103, not sm_103a). Use
// ldmatrix + mma.sync.m16n8k16 bf16 with 3-term bf16 split
// (hi*hi + hi*lo + lo*hi), fp32 register accumulators. Triangular tiles kept.

#define B_SZ 4096
#define D_SZ 512
#define BM 128
#define BN 128
#define NB (B_SZ / BM)              /* 32 block-rows */
#define NTILES (NB * (NB + 1) / 2)  /* 528 upper-triangular tiles */
#define MARGIN_F 0.5f

#define KCHUNK 64                        /* bf16 per K chunk (128B rows, SW128) */
#define NCHUNK (D_SZ / KCHUNK)           /* 8 */
#define TILE_BYTES (128 * KCHUNK * 2)    /* 16384 */
#define BUF_BYTES  (4 * TILE_BYTES)      /* Ahi,Alo,Bhi,Blo = 65536 */
#define SMEM_DYN   (2 * BUF_BYTES + 1024)

// ------------------------- device scratch -------------------------
__device__ float          g_norms[B_SZ];
__device__ int            g_hp_bits[B_SZ];
__device__ int            g_hn_bits[B_SZ];
__device__ int            g_labels[B_SZ];
__device__ int            g_is64;
__device__ __nv_bfloat16  g_xhi[B_SZ * D_SZ];
__device__ __nv_bfloat16  g_xlo[B_SZ * D_SZ];

// ------------------------- PTX helpers -------------------------
__device__ __forceinline__ uint32_t smem_u32(const void* p) {
    uint32_t a;
    asm("{ .reg .u64 t; cvta.to.shared.u64 t, %1; cvt.u32.u64 %0, t; }" : "=r"(a) : "l"(p));
    return a;
}
#define CP_ASYNC16(dst, src) \
    asm volatile("cp.async.cg.shared.global [%0], [%1], 16;" :: "r"(dst), "l"(src) : "memory")
#define CP_ASYNC_COMMIT() asm volatile("cp.async.commit_group;" ::: "memory")
#define CP_ASYNC_WAIT(n)  asm volatile("cp.async.wait_group %0;" :: "n"(n) : "memory")

__device__ __forceinline__ void ldsm_x4(uint32_t* r, uint32_t addr) {
    asm volatile("ldmatrix.sync.aligned.m8n8.x4.shared.b16 {%0,%1,%2,%3}, [%4];"
        : "=r"(r[0]), "=r"(r[1]), "=r"(r[2]), "=r"(r[3]) : "r"(addr));
}
__device__ __forceinline__ void mma16816(float* c, const uint32_t* a, const uint32_t* b) {
    asm volatile("mma.sync.aligned.m16n8k16.row.col.f32.bf16.bf16.f32 "
        "{%0,%1,%2,%3}, {%4,%5,%6,%7}, {%8,%9}, {%0,%1,%2,%3};"
        : "+f"(c[0]), "+f"(c[1]), "+f"(c[2]), "+f"(c[3])
        : "r"(a[0]), "r"(a[1]), "r"(a[2]), "r"(a[3]), "r"(b[0]), "r"(b[1]));
}

// ------------------------- small kernels -------------------------
__global__ void detect_kernel(const long long* __restrict__ lab64) {
    if (threadIdx.x == 0) {
        int ok = 1;
        #pragma unroll
        for (int k = 0; k < 16; k++) {
            long long v = lab64[k];
            if (v < 0 || v >= (1LL << 31)) ok = 0;
        }
        g_is64 = ok;
    }
}

__global__ void convert_labels_kernel(const void* __restrict__ labp) {
    int i = blockIdx.x * blockDim.x + threadIdx.x;
    if (i < B_SZ) {
        if (g_is64) g_labels[i] = (int)((const long long*)labp)[i];
        else        g_labels[i] = ((const int*)labp)[i];
    }
}

// fp32 -> (hi, lo) bf16 split, 4 elements per thread
__global__ void hilo_kernel(const float* __restrict__ X) {
    int i = blockIdx.x * blockDim.x + threadIdx.x;   // float4 index
    float4 v = ((const float4*)X)[i];
    __nv_bfloat16 h[4], l[4];
    float f[4] = {v.x, v.y, v.z, v.w};
    #pragma unroll
    for (int k = 0; k < 4; k++) {
        h[k] = __float2bfloat16_rn(f[k]);
        l[k] = __float2bfloat16_rn(f[k] - __bfloat162float(h[k]));
    }
    ((uint2*)g_xhi)[i] = *(uint2*)h;
    ((uint2*)g_xlo)[i] = *(uint2*)l;
}

__global__ void prep_kernel(const float* __restrict__ X) {
    int w    = blockIdx.x * (blockDim.x >> 5) + (threadIdx.x >> 5);
    int lane = threadIdx.x & 31;
    if (w >= B_SZ) return;
    const float* row = X + (size_t)w * D_SZ;
    float s = 0.f;
    #pragma unroll
    for (int k = lane; k < D_SZ; k += 32) {
        float v = row[k];
        s = fmaf(v, v, s);
    }
    #pragma unroll
    for (int m = 16; m >= 1; m >>= 1)
        s += __shfl_down_sync(0xffffffffu, s, m);
    if (lane == 0) {
        g_norms[w]   = s;
        g_hp_bits[w] = (int)0xFF800000;  // -inf
        g_hn_bits[w] = 0x7F800000;       // +inf
    }
}

// ------------------------- chunk loader -------------------------
// 4 tiles (Ahi,Alo,Bhi,Blo), 128 rows x 64 bf16 each, SW128 swizzled.
__device__ __forceinline__ void load_chunk(int chunk, uint32_t bufBase,
                                           int rowBase, int colBase, int tid) {
    const int k0 = chunk * KCHUNK;
    const __nv_bfloat16* srcs[4] = {
        g_xhi + (size_t)rowBase * D_SZ,
        g_xlo + (size_t)rowBase * D_SZ,
        g_xhi + (size_t)colBase * D_SZ,
        g_xlo + (size_t)colBase * D_SZ
    };
    #pragma unroll
    for (int i = 0; i < 16; i++) {
        int seg  = tid + i * 256;          // 0..4095
        int c16  = seg & 7;                // 16B segment within row
        int row  = (seg >> 3) & 127;
        int tile = seg >> 10;              // 0..3
        uint32_t off = (uint32_t)(row * 128 + c16 * 16);
        uint32_t sw  = off ^ ((off >> 3) & 0x70);
        uint32_t dst = bufBase + (uint32_t)tile * TILE_BYTES + sw;
        const char* src = (const char*)srcs[tile] + ((size_t)row * D_SZ + k0 + c16 * 8) * 2;
        CP_ASYNC16(dst, src);
    }
    CP_ASYNC_COMMIT();
}

// ------------------------- main tensor-core tile kernel -------------------------
__global__ __launch_bounds__(256, 1) void tile_kernel() {
    extern __shared__ char dsmem[];
    __shared__ int   labB[BN];
    __shared__ float nrmB[BN];

    // ---- triangular tile decode: blockIdx.x -> (by, bx), bx >= by ----
    const int t = blockIdx.x;
    float ff = (float)(2 * NB + 1);
    int by = (int)((ff - sqrtf(ff * ff - 8.0f * (float)t)) * 0.5f);
    if (by < 0) by = 0;
    if (by > NB - 1) by = NB - 1;
    while (by > 0 && (by * NB - by * (by - 1) / 2) > t) by--;
    while (((by + 1) * NB - (by + 1) * by / 2) <= t) by++;
    const int bx   = by + (t - (by * NB - by * (by - 1) / 2));
    const bool diag = (bx == by);

    const int rowBase = by * BM;
    const int colBase = bx * BN;
    const int tid  = threadIdx.x;
    const int wid  = tid >> 5;
    const int lane = tid & 31;

    uint32_t dynBase = (smem_u32(dsmem) + 1023u) & ~1023u;

    if (tid < BN) {
        labB[tid] = g_labels[colBase + tid];
        nrmB[tid] = g_norms[colBase + tid];
    }

    // ---- prologue loads ----
    load_chunk(0, dynBase, rowBase, colBase, tid);
    load_chunk(1, dynBase + BUF_BYTES, rowBase, colBase, tid);

    // ---- per-thread ldmatrix address parts ----
    // A x4 (16x16): lanes 0-7 m0-7@k0 | 8-15 m8-15@k0 | 16-23 m0-7@k8 | 24-31 m8-15@k8
    const int aRowIn = (lane & 7) + ((lane >> 3) & 1) * 8;
    const int aKH    = ((lane >> 4) & 1) * 16;            // bytes
    // B x4 (two n8k16 frags): 0-7 n0-7@k0 | 8-15 n0-7@k8 | 16-23 n8-15@k0 | 24-31 n8-15@k8
    const int bNIn = (lane & 7) + ((lane >> 4) & 1) * 8;
    const int bKH  = ((lane >> 3) & 1) * 16;              // bytes

    const int warpRow0 = (wid & 1) * 64;                  // rows within tile
    const int warpCol0 = (wid >> 1) * 32;                 // cols within tile

    uint32_t aOff[4];
    #pragma unroll
    for (int fm = 0; fm < 4; fm++)
        aOff[fm] = (uint32_t)(warpRow0 + fm * 16 + aRowIn) * 128u;
    const uint32_t aMsk = (uint32_t)(aRowIn & 7) << 4;    // swizzle xor mask (row bits)
    uint32_t bOff[2];
    bOff[0] = (uint32_t)(warpCol0 + bNIn) * 128u;
    bOff[1] = (uint32_t)(warpCol0 + 16 + bNIn) * 128u;
    const uint32_t bMsk = (uint32_t)(bNIn & 7) << 4;

    float Cacc[4][4][4];
    #pragma unroll
    for (int i = 0; i < 4; i++)
        #pragma unroll
        for (int j = 0; j < 4; j++)
            #pragma unroll
            for (int k = 0; k < 4; k++) Cacc[i][j][k] = 0.f;

    // ---- pipelined main loop over 8 K-chunks ----
    for (int c = 0; c < NCHUNK; c++) {
        if (c < NCHUNK - 1) { CP_ASYNC_WAIT(1); } else { CP_ASYNC_WAIT(0); }
        __syncthreads();                       // chunk c resident (and labB on c==0)

        const uint32_t bb  = dynBase + (uint32_t)(c & 1) * BUF_BYTES;
        const uint32_t sAh = bb;
        const uint32_t sAl = bb + TILE_BYTES;
        const uint32_t sBh = bb + 2 * TILE_BYTES;
        const uint32_t sBl = bb + 3 * TILE_BYTES;

        #pragma unroll
        for (int ks = 0; ks < 4; ks++) {
            const uint32_t akb = ((uint32_t)(ks * 32 + aKH)) ^ aMsk;
            const uint32_t bkb = ((uint32_t)(ks * 32 + bKH)) ^ bMsk;
            uint32_t bh[8], bl[8];
            ldsm_x4(bh,     sBh + bOff[0] + bkb);
            ldsm_x4(bh + 4, sBh + bOff[1] + bkb);
            ldsm_x4(bl,     sBl + bOff[0] + bkb);
            ldsm_x4(bl + 4, sBl + bOff[1] + bkb);
            #pragma unroll
            for (int fm = 0; fm < 4; fm++) {
                uint32_t a[4];
                ldsm_x4(a, sAh + aOff[fm] + akb);
                #pragma unroll
                for (int fn = 0; fn < 4; fn++) mma16816(Cacc[fm][fn], a, bh + fn * 2);
                #pragma unroll
                for (int fn = 0; fn < 4; fn++) mma16816(Cacc[fm][fn], a, bl + fn * 2);
                ldsm_x4(a, sAl + aOff[fm] + akb);
                #pragma unroll
                for (int fn = 0; fn < 4; fn++) mma16816(Cacc[fm][fn], a, bh + fn * 2);
            }
        }

        if (c + 2 < NCHUNK) {
            __syncthreads();                   // all warps done reading this buffer
            load_chunk(c + 2, dynBase + (uint32_t)(c & 1) * BUF_BYTES,
                       rowBase, colBase, tid);
        }
    }

    // ---- epilogue: distances + hardest pos/neg from register fragments ----
    const float NEG_INF = __int_as_float(0xFF800000);
    const float POS_INF = __int_as_float(0x7F800000);
    const int quad = lane >> 2;      // 0..7  (row within 8-row group)
    const int pos  = lane & 3;       // 0..3  (col pair)

    int   laR[8], giR[8];
    float naR[8];
    #pragma unroll
    for (int fm = 0; fm < 4; fm++)
        #pragma unroll
        for (int ar = 0; ar < 2; ar++) {
            int gi = rowBase + warpRow0 + fm * 16 + ar * 8 + quad;
            giR[fm * 2 + ar] = gi;
            laR[fm * 2 + ar] = g_labels[gi];
            naR[fm * 2 + ar] = g_norms[gi];
        }
    int   lbC[8], gjC[8];
    float nbC[8];
    #pragma unroll
    for (int fn = 0; fn < 4; fn++)
        #pragma unroll
        for (int cb = 0; cb < 2; cb++) {
            int cl = warpCol0 + fn * 8 + pos * 2 + cb;
            gjC[fn * 2 + cb] = colBase + cl;
            lbC[fn * 2 + cb] = labB[cl];
            nbC[fn * 2 + cb] = nrmB[cl];
        }

    float hpR[8], hnR[8], hpc[8], hnc[8];
    #pragma unroll
    for (int i = 0; i < 8; i++) { hpR[i] = NEG_INF; hnR[i] = POS_INF; hpc[i] = NEG_INF; hnc[i] = POS_INF; }

    #pragma unroll
    for (int fm = 0; fm < 4; fm++)
        #pragma unroll
        for (int fn = 0; fn < 4; fn++)
            #pragma unroll
            for (int ar = 0; ar < 2; ar++)
                #pragma unroll
                for (int cb = 0; cb < 2; cb++) {
                    int ri = fm * 2 + ar, ci = fn * 2 + cb;
                    float dot = Cacc[fm][fn][ar * 2 + cb];
                    float sq  = fmaxf(fmaf(-2.f, dot, naR[ri] + nbC[ci]), 0.f);
                    float d   = sqrtf(sq);
                    if (laR[ri] == lbC[ci]) {
                        if (giR[ri] != gjC[ci]) {
                            hpR[ri] = fmaxf(hpR[ri], d);
                            hpc[ci] = fmaxf(hpc[ci], d);
                        }
                    } else {
                        hnR[ri] = fminf(hnR[ri], d);
                        hnc[ci] = fminf(hnc[ci], d);
                    }
                }

    // row stats: reduce over the 4 'pos' lanes sharing a row
    #pragma unroll
    for (int i = 0; i < 8; i++) {
        float a = hpR[i], b = hnR[i];
        a = fmaxf(a, __shfl_xor_sync(0xffffffffu, a, 1));
        a = fmaxf(a, __shfl_xor_sync(0xffffffffu, a, 2));
        b = fminf(b, __shfl_xor_sync(0xffffffffu, b, 1));
        b = fminf(b, __shfl_xor_sync(0xffffffffu, b, 2));
        if (pos == 0) {
            atomicMax(&g_hp_bits[giR[i]], __float_as_int(a));
            atomicMin(&g_hn_bits[giR[i]], __float_as_int(b));
        }
    }
    // column stats (symmetry): reduce over the 8 'quad' lanes sharing a column
    if (!diag) {
        #pragma unroll
        for (int i = 0; i < 8; i++) {
            float a = hpc[i], b = hnc[i];
            a = fmaxf(a, __shfl_xor_sync(0xffffffffu, a, 4));
            a = fmaxf(a, __shfl_xor_sync(0xffffffffu, a, 8));
            a = fmaxf(a, __shfl_xor_sync(0xffffffffu, a, 16));
            b = fminf(b, __shfl_xor_sync(0xffffffffu, b, 4));
            b = fminf(b, __shfl_xor_sync(0xffffffffu, b, 8));
            b = fminf(b, __shfl_xor_sync(0xffffffffu, b, 16));
            if (quad == 0) {
                atomicMax(&g_hp_bits[gjC[i]], __float_as_int(a));
                atomicMin(&g_hn_bits[gjC[i]], __float_as_int(b));
            }
        }
    }
}

// ------------------------- finalize -------------------------
__global__ void finalize_kernel(float* __restrict__ out) {
    __shared__ float ssum[1024];
    __shared__ int   scnt[1024];
    int t = threadIdx.x;
    float sum = 0.f;
    int cnt = 0;
    for (int i = t; i < B_SZ; i += 1024) {
        int hpb = g_hp_bits[i];
        int hnb = g_hn_bits[i];
        bool valid = (hpb != (int)0xFF800000) && (hnb != 0x7F800000);
        if (valid) {
            float hp = __int_as_float(hpb);
            float hn = __int_as_float(hnb);
            sum += fmaxf(hp - hn + MARGIN_F, 0.f);
            cnt += 1;
        }
    }
    ssum[t] = sum;
    scnt[t] = cnt;
    __syncthreads();
    for (int s = 512; s >= 1; s >>= 1) {
        if (t < s) {
            ssum[t] += ssum[t + s];
            scnt[t] += scnt[t + s];
        }
        __syncthreads();
    }
    if (t == 0) out[0] = (scnt[0] > 0) ? (ssum[0] / (float)scnt[0]) : 0.f;
}

// ------------------------- launch -------------------------
extern "C" void kernel_launch(void* const* d_in, const int* in_sizes, int n_in,
                              void* d_out, int out_size) {
    const float* X    = (const float*)d_in[0];
    const void*  labp = d_in[1];
    float*       out  = (float*)d_out;

    // idempotent, host-side, not a stream op: safe under graph capture
    cudaFuncSetAttribute(tile_kernel, cudaFuncAttributeMaxDynamicSharedMemorySize, SMEM_DYN);

    detect_kernel<<<1, 32>>>((const long long*)labp);
    convert_labels_kernel<<<(B_SZ + 255) / 256, 256>>>(labp);
    hilo_kernel<<<(B_SZ * D_SZ / 4) / 256, 256>>>(X);
    prep_kernel<<<B_SZ / 8, 256>>>(X);

    tile_kernel<<<NTILES, 256, SMEM_DYN>>>();

    finalize_kernel<<<1, 1024>>>(out);
}

// round 11
// speedup vs baseline: 9.5902x; 2.0983x over previous
#include <cuda_runtime.h>
#include <cuda_fp16.h>
#include <math.h>
#include <stdint.h>

// HardTripletLoss on GB300 (base sm_103 target): HMMA fp16 Gram GEMM + fused
// hardest pos/neg. B=4096, D=512, 64 classes, margin=0.5.
// R10: fp16 single-term GEMM (error averages out in the final mean), 2 CTAs/SM,
// fused prep kernels. Triangular tiles + register-fragment epilogue kept.

#define B_SZ 4096
#define D_SZ 512
#define BM 128
#define BN 128
#define NB (B_SZ / BM)              /* 32 block-rows */
#define NTILES (NB * (NB + 1) / 2)  /* 528 upper-triangular tiles */
#define MARGIN_F 0.5f

#define KCHUNK 64                        /* fp16 per K chunk (128B rows, SW128) */
#define NCHUNK (D_SZ / KCHUNK)           /* 8 */
#define TILE_BYTES (128 * KCHUNK * 2)    /* 16384 */
#define BUF_BYTES  (2 * TILE_BYTES)      /* A, B tiles = 32768 */
#define SMEM_DYN   (2 * BUF_BYTES + 1024)

// ------------------------- device scratch -------------------------
__device__ float   g_norms[B_SZ];
__device__ int     g_hp_bits[B_SZ];
__device__ int     g_hn_bits[B_SZ];
__device__ int     g_labels[B_SZ];
__device__ __half  g_xh[B_SZ * D_SZ];

// ------------------------- PTX helpers -------------------------
__device__ __forceinline__ uint32_t smem_u32(const void* p) {
    uint32_t a;
    asm("{ .reg .u64 t; cvta.to.shared.u64 t, %1; cvt.u32.u64 %0, t; }" : "=r"(a) : "l"(p));
    return a;
}
#define CP_ASYNC16(dst, src) \
    asm volatile("cp.async.cg.shared.global [%0], [%1], 16;" :: "r"(dst), "l"(src) : "memory")
#define CP_ASYNC_COMMIT() asm volatile("cp.async.commit_group;" ::: "memory")
#define CP_ASYNC_WAIT(n)  asm volatile("cp.async.wait_group %0;" :: "n"(n) : "memory")

__device__ __forceinline__ void ldsm_x4(uint32_t* r, uint32_t addr) {
    asm volatile("ldmatrix.sync.aligned.m8n8.x4.shared.b16 {%0,%1,%2,%3}, [%4];"
        : "=r"(r[0]), "=r"(r[1]), "=r"(r[2]), "=r"(r[3]) : "r"(addr));
}
__device__ __forceinline__ void mma16816(float* c, const uint32_t* a, const uint32_t* b) {
    asm volatile("mma.sync.aligned.m16n8k16.row.col.f32.f16.f16.f32 "
        "{%0,%1,%2,%3}, {%4,%5,%6,%7}, {%8,%9}, {%0,%1,%2,%3};"
        : "+f"(c[0]), "+f"(c[1]), "+f"(c[2]), "+f"(c[3])
        : "r"(a[0]), "r"(a[1]), "r"(a[2]), "r"(a[3]), "r"(b[0]), "r"(b[1]));
}

// ------------------------- fused label kernel -------------------------
// Detect int64 vs int32 labels, then normalize into g_labels. One block.
__global__ void labels_kernel(const void* __restrict__ labp) {
    __shared__ int is64;
    if (threadIdx.x == 0) {
        const long long* lab64 = (const long long*)labp;
        int ok = 1;
        #pragma unroll
        for (int k = 0; k < 16; k++) {
            long long v = lab64[k];
            if (v < 0 || v >= (1LL << 31)) ok = 0;
        }
        is64 = ok;
    }
    __syncthreads();
    const int use64 = is64;
    for (int i = threadIdx.x; i < B_SZ; i += blockDim.x) {
        g_labels[i] = use64 ? (int)((const long long*)labp)[i]
                            : ((const int*)labp)[i];
    }
}

// ------------------------- fused prep: norms + fp16 convert + init ----------
// One warp per row; reads X once.
__global__ void prep_kernel(const float* __restrict__ X) {
    const int w    = blockIdx.x * 8 + (threadIdx.x >> 5);
    const int lane = threadIdx.x & 31;
    const float4* row = (const float4*)(X + (size_t)w * D_SZ);
    uint2*        dst = (uint2*)(g_xh + (size_t)w * D_SZ);
    float s = 0.f;
    #pragma unroll
    for (int i = 0; i < 4; i++) {
        float4 v = row[lane + 32 * i];
        s = fmaf(v.x, v.x, s);
        s = fmaf(v.y, v.y, s);
        s = fmaf(v.z, v.z, s);
        s = fmaf(v.w, v.w, s);
        __half h[4];
        h[0] = __float2half_rn(v.x);
        h[1] = __float2half_rn(v.y);
        h[2] = __float2half_rn(v.z);
        h[3] = __float2half_rn(v.w);
        dst[lane + 32 * i] = *(uint2*)h;
    }
    #pragma unroll
    for (int m = 16; m >= 1; m >>= 1)
        s += __shfl_down_sync(0xffffffffu, s, m);
    if (lane == 0) {
        g_norms[w]   = s;
        g_hp_bits[w] = (int)0xFF800000;  // -inf
        g_hn_bits[w] = 0x7F800000;       // +inf
    }
}

// ------------------------- chunk loader -------------------------
// 2 tiles (A, B), 128 rows x 64 fp16 each (128B rows), SW128 swizzled.
__device__ __forceinline__ void load_chunk(int chunk, uint32_t bufBase,
                                           int rowBase, int colBase, int tid) {
    const int k0 = chunk * KCHUNK;
    const __half* srcA = g_xh + (size_t)rowBase * D_SZ;
    const __half* srcB = g_xh + (size_t)colBase * D_SZ;
    #pragma unroll
    for (int i = 0; i < 8; i++) {
        int seg  = tid + i * 256;          // 0..2047
        int c16  = seg & 7;                // 16B segment within row
        int row  = (seg >> 3) & 127;
        int tile = seg >> 10;              // 0 = A, 1 = B
        uint32_t off = (uint32_t)(row * 128 + c16 * 16);
        uint32_t sw  = off ^ ((off >> 3) & 0x70);
        uint32_t dst = bufBase + (uint32_t)tile * TILE_BYTES + sw;
        const __half* base = tile ? srcB : srcA;
        const char* src = (const char*)base + ((size_t)row * D_SZ + k0 + c16 * 8) * 2;
        CP_ASYNC16(dst, src);
    }
    CP_ASYNC_COMMIT();
}

// ------------------------- main tensor-core tile kernel -------------------------
__global__ __launch_bounds__(256, 2) void tile_kernel() {
    extern __shared__ char dsmem[];
    __shared__ int   labB[BN];
    __shared__ float nrmB[BN];

    // ---- triangular tile decode: blockIdx.x -> (by, bx), bx >= by ----
    const int t = blockIdx.x;
    float ff = (float)(2 * NB + 1);
    int by = (int)((ff - sqrtf(ff * ff - 8.0f * (float)t)) * 0.5f);
    if (by < 0) by = 0;
    if (by > NB - 1) by = NB - 1;
    while (by > 0 && (by * NB - by * (by - 1) / 2) > t) by--;
    while (((by + 1) * NB - (by + 1) * by / 2) <= t) by++;
    const int bx   = by + (t - (by * NB - by * (by - 1) / 2));
    const bool diag = (bx == by);

    const int rowBase = by * BM;
    const int colBase = bx * BN;
    const int tid  = threadIdx.x;
    const int wid  = tid >> 5;
    const int lane = tid & 31;

    uint32_t dynBase = (smem_u32(dsmem) + 1023u) & ~1023u;

    if (tid < BN) {
        labB[tid] = g_labels[colBase + tid];
        nrmB[tid] = g_norms[colBase + tid];
    }

    // ---- prologue loads ----
    load_chunk(0, dynBase, rowBase, colBase, tid);
    load_chunk(1, dynBase + BUF_BYTES, rowBase, colBase, tid);

    // ---- per-thread ldmatrix address parts ----
    const int aRowIn = (lane & 7) + ((lane >> 3) & 1) * 8;
    const int aKH    = ((lane >> 4) & 1) * 16;            // bytes
    const int bNIn = (lane & 7) + ((lane >> 4) & 1) * 8;
    const int bKH  = ((lane >> 3) & 1) * 16;              // bytes

    const int warpRow0 = (wid & 1) * 64;                  // rows within tile
    const int warpCol0 = (wid >> 1) * 32;                 // cols within tile

    uint32_t aOff[4];
    #pragma unroll
    for (int fm = 0; fm < 4; fm++)
        aOff[fm] = (uint32_t)(warpRow0 + fm * 16 + aRowIn) * 128u;
    const uint32_t aMsk = (uint32_t)(aRowIn & 7) << 4;
    uint32_t bOff[2];
    bOff[0] = (uint32_t)(warpCol0 + bNIn) * 128u;
    bOff[1] = (uint32_t)(warpCol0 + 16 + bNIn) * 128u;
    const uint32_t bMsk = (uint32_t)(bNIn & 7) << 4;

    float Cacc[4][4][4];
    #pragma unroll
    for (int i = 0; i < 4; i++)
        #pragma unroll
        for (int j = 0; j < 4; j++)
            #pragma unroll
            for (int k = 0; k < 4; k++) Cacc[i][j][k] = 0.f;

    // ---- pipelined main loop over 8 K-chunks ----
    for (int c = 0; c < NCHUNK; c++) {
        if (c < NCHUNK - 1) { CP_ASYNC_WAIT(1); } else { CP_ASYNC_WAIT(0); }
        __syncthreads();                       // chunk c resident (and labB on c==0)

        const uint32_t bb = dynBase + (uint32_t)(c & 1) * BUF_BYTES;
        const uint32_t sA = bb;
        const uint32_t sB = bb + TILE_BYTES;

        #pragma unroll
        for (int ks = 0; ks < 4; ks++) {
            const uint32_t akb = ((uint32_t)(ks * 32 + aKH)) ^ aMsk;
            const uint32_t bkb = ((uint32_t)(ks * 32 + bKH)) ^ bMsk;
            uint32_t bh[8];
            ldsm_x4(bh,     sB + bOff[0] + bkb);
            ldsm_x4(bh + 4, sB + bOff[1] + bkb);
            #pragma unroll
            for (int fm = 0; fm < 4; fm++) {
                uint32_t a[4];
                ldsm_x4(a, sA + aOff[fm] + akb);
                #pragma unroll
                for (int fn = 0; fn < 4; fn++) mma16816(Cacc[fm][fn], a, bh + fn * 2);
            }
        }

        if (c + 2 < NCHUNK) {
            __syncthreads();                   // all warps done reading this buffer
            load_chunk(c + 2, dynBase + (uint32_t)(c & 1) * BUF_BYTES,
                       rowBase, colBase, tid);
        }
    }

    // ---- epilogue: distances + hardest pos/neg from register fragments ----
    const float NEG_INF = __int_as_float(0xFF800000);
    const float POS_INF = __int_as_float(0x7F800000);
    const int quad = lane >> 2;      // 0..7  (row within 8-row group)
    const int pos  = lane & 3;       // 0..3  (col pair)

    int   laR[8], giR[8];
    float naR[8];
    #pragma unroll
    for (int fm = 0; fm < 4; fm++)
        #pragma unroll
        for (int ar = 0; ar < 2; ar++) {
            int gi = rowBase + warpRow0 + fm * 16 + ar * 8 + quad;
            giR[fm * 2 + ar] = gi;
            laR[fm * 2 + ar] = g_labels[gi];
            naR[fm * 2 + ar] = g_norms[gi];
        }
    int   lbC[8], gjC[8];
    float nbC[8];
    #pragma unroll
    for (int fn = 0; fn < 4; fn++)
        #pragma unroll
        for (int cb = 0; cb < 2; cb++) {
            int cl = warpCol0 + fn * 8 + pos * 2 + cb;
            gjC[fn * 2 + cb] = colBase + cl;
            lbC[fn * 2 + cb] = labB[cl];
            nbC[fn * 2 + cb] = nrmB[cl];
        }

    float hpR[8], hnR[8], hpc[8], hnc[8];
    #pragma unroll
    for (int i = 0; i < 8; i++) { hpR[i] = NEG_INF; hnR[i] = POS_INF; hpc[i] = NEG_INF; hnc[i] = POS_INF; }

    #pragma unroll
    for (int fm = 0; fm < 4; fm++)
        #pragma unroll
        for (int fn = 0; fn < 4; fn++)
            #pragma unroll
            for (int ar = 0; ar < 2; ar++)
                #pragma unroll
                for (int cb = 0; cb < 2; cb++) {
                    int ri = fm * 2 + ar, ci = fn * 2 + cb;
                    float dot = Cacc[fm][fn][ar * 2 + cb];
                    float sq  = fmaxf(fmaf(-2.f, dot, naR[ri] + nbC[ci]), 0.f);
                    float d   = sqrtf(sq);
                    if (laR[ri] == lbC[ci]) {
                        if (giR[ri] != gjC[ci]) {
                            hpR[ri] = fmaxf(hpR[ri], d);
                            hpc[ci] = fmaxf(hpc[ci], d);
                        }
                    } else {
                        hnR[ri] = fminf(hnR[ri], d);
                        hnc[ci] = fminf(hnc[ci], d);
                    }
                }

    // row stats: reduce over the 4 'pos' lanes sharing a row
    #pragma unroll
    for (int i = 0; i < 8; i++) {
        float a = hpR[i], b = hnR[i];
        a = fmaxf(a, __shfl_xor_sync(0xffffffffu, a, 1));
        a = fmaxf(a, __shfl_xor_sync(0xffffffffu, a, 2));
        b = fminf(b, __shfl_xor_sync(0xffffffffu, b, 1));
        b = fminf(b, __shfl_xor_sync(0xffffffffu, b, 2));
        if (pos == 0) {
            atomicMax(&g_hp_bits[giR[i]], __float_as_int(a));
            atomicMin(&g_hn_bits[giR[i]], __float_as_int(b));
        }
    }
    // column stats (symmetry): reduce over the 8 'quad' lanes sharing a column
    if (!diag) {
        #pragma unroll
        for (int i = 0; i < 8; i++) {
            float a = hpc[i], b = hnc[i];
            a = fmaxf(a, __shfl_xor_sync(0xffffffffu, a, 4));
            a = fmaxf(a, __shfl_xor_sync(0xffffffffu, a, 8));
            a = fmaxf(a, __shfl_xor_sync(0xffffffffu, a, 16));
            b = fminf(b, __shfl_xor_sync(0xffffffffu, b, 4));
            b = fminf(b, __shfl_xor_sync(0xffffffffu, b, 8));
            b = fminf(b, __shfl_xor_sync(0xffffffffu, b, 16));
            if (quad == 0) {
                atomicMax(&g_hp_bits[gjC[i]], __float_as_int(a));
                atomicMin(&g_hn_bits[gjC[i]], __float_as_int(b));
            }
        }
    }
}

// ------------------------- finalize -------------------------
__global__ void finalize_kernel(float* __restrict__ out) {
    __shared__ float ssum[1024];
    __shared__ int   scnt[1024];
    int t = threadIdx.x;
    float sum = 0.f;
    int cnt = 0;
    for (int i = t; i < B_SZ; i += 1024) {
        int hpb = g_hp_bits[i];
        int hnb = g_hn_bits[i];
        bool valid = (hpb != (int)0xFF800000) && (hnb != 0x7F800000);
        if (valid) {
            float hp = __int_as_float(hpb);
            float hn = __int_as_float(hnb);
            sum += fmaxf(hp - hn + MARGIN_F, 0.f);
            cnt += 1;
        }
    }
    ssum[t] = sum;
    scnt[t] = cnt;
    __syncthreads();
    for (int s = 512; s >= 1; s >>= 1) {
        if (t < s) {
            ssum[t] += ssum[t + s];
            scnt[t] += scnt[t + s];
        }
        __syncthreads();
    }
    if (t == 0) out[0] = (scnt[0] > 0) ? (ssum[0] / (float)scnt[0]) : 0.f;
}

// ------------------------- launch -------------------------
extern "C" void kernel_launch(void* const* d_in, const int* in_sizes, int n_in,
                              void* d_out, int out_size) {
    const float* X    = (const float*)d_in[0];
    const void*  labp = d_in[1];
    float*       out  = (float*)d_out;

    // idempotent, host-side, not a stream op: safe under graph capture
    cudaFuncSetAttribute(tile_kernel, cudaFuncAttributeMaxDynamicSharedMemorySize, SMEM_DYN);

    labels_kernel<<<1, 1024>>>(labp);
    prep_kernel<<<B_SZ / 8, 256>>>(X);

    tile_kernel<<<NTILES, 256, SMEM_DYN>>>();

    finalize_kernel<<<1, 1024>>>(out);
}

// round 13
// speedup vs baseline: 10.1191x; 1.0551x over previous
#include <cuda_runtime.h>
#include <cuda_fp16.h>
#include <math.h>
#include <stdint.h>

// HardTripletLoss on GB300 (base sm_103 target): HMMA fp16 Gram GEMM + fused
// hardest pos/neg + fused finalize. B=4096, D=512, 64 classes, margin=0.5.
// R12 (resubmit after infra failure): labels folded into prep (block 0),
// finalize folded into tile_kernel (last-CTA-done) -> 2 launches total.

#define B_SZ 4096
#define D_SZ 512
#define BM 128
#define BN 128
#define NB (B_SZ / BM)              /* 32 block-rows */
#define NTILES (NB * (NB + 1) / 2)  /* 528 upper-triangular tiles */
#define MARGIN_F 0.5f

#define KCHUNK 64                        /* fp16 per K chunk (128B rows, SW128) */
#define NCHUNK (D_SZ / KCHUNK)           /* 8 */
#define TILE_BYTES (128 * KCHUNK * 2)    /* 16384 */
#define BUF_BYTES  (2 * TILE_BYTES)      /* A, B tiles = 32768 */
#define SMEM_DYN   (2 * BUF_BYTES + 1024)

// ------------------------- device scratch -------------------------
__device__ float        g_norms[B_SZ];
__device__ int          g_hp_bits[B_SZ];
__device__ int          g_hn_bits[B_SZ];
__device__ int          g_labels[B_SZ];
__device__ unsigned int g_tiles_done;

__device__ __half  g_xh[B_SZ * D_SZ];

// ------------------------- PTX helpers -------------------------
__device__ __forceinline__ uint32_t smem_u32(const void* p) {
    uint32_t a;
    asm("{ .reg .u64 t; cvta.to.shared.u64 t, %1; cvt.u32.u64 %0, t; }" : "=r"(a) : "l"(p));
    return a;
}
#define CP_ASYNC16(dst, src) \
    asm volatile("cp.async.cg.shared.global [%0], [%1], 16;" :: "r"(dst), "l"(src) : "memory")
#define CP_ASYNC_COMMIT() asm volatile("cp.async.commit_group;" ::: "memory")
#define CP_ASYNC_WAIT(n)  asm volatile("cp.async.wait_group %0;" :: "n"(n) : "memory")

__device__ __forceinline__ void ldsm_x4(uint32_t* r, uint32_t addr) {
    asm volatile("ldmatrix.sync.aligned.m8n8.x4.shared.b16 {%0,%1,%2,%3}, [%4];"
        : "=r"(r[0]), "=r"(r[1]), "=r"(r[2]), "=r"(r[3]) : "r"(addr));
}
__device__ __forceinline__ void mma16816(float* c, const uint32_t* a, const uint32_t* b) {
    asm volatile("mma.sync.aligned.m16n8k16.row.col.f32.f16.f16.f32 "
        "{%0,%1,%2,%3}, {%4,%5,%6,%7}, {%8,%9}, {%0,%1,%2,%3};"
        : "+f"(c[0]), "+f"(c[1]), "+f"(c[2]), "+f"(c[3])
        : "r"(a[0]), "r"(a[1]), "r"(a[2]), "r"(a[3]), "r"(b[0]), "r"(b[1]));
}

// ------------------------- fused prep -------------------------
// All blocks: row norms + fp16 convert + hp/hn init (one warp per row).
// Block 0 additionally: label dtype detect + normalize, reset done-counter.
__global__ void prep_kernel(const float* __restrict__ X, const void* __restrict__ labp) {
    if (blockIdx.x == 0) {
        __shared__ int is64;
        if (threadIdx.x == 0) {
            const long long* lab64 = (const long long*)labp;
            int ok = 1;
            #pragma unroll
            for (int k = 0; k < 16; k++) {
                long long v = lab64[k];
                if (v < 0 || v >= (1LL << 31)) ok = 0;
            }
            is64 = ok;
            g_tiles_done = 0u;
        }
        __syncthreads();
        const int use64 = is64;
        #pragma unroll
        for (int i = 0; i < B_SZ / 256; i++) {
            int idx = threadIdx.x + i * 256;
            g_labels[idx] = use64 ? (int)((const long long*)labp)[idx]
                                  : ((const int*)labp)[idx];
        }
    }

    const int w    = blockIdx.x * 8 + (threadIdx.x >> 5);
    const int lane = threadIdx.x & 31;
    const float4* row = (const float4*)(X + (size_t)w * D_SZ);
    uint2*        dst = (uint2*)(g_xh + (size_t)w * D_SZ);
    float s = 0.f;
    #pragma unroll
    for (int i = 0; i < 4; i++) {
        float4 v = row[lane + 32 * i];
        s = fmaf(v.x, v.x, s);
        s = fmaf(v.y, v.y, s);
        s = fmaf(v.z, v.z, s);
        s = fmaf(v.w, v.w, s);
        __half h[4];
        h[0] = __float2half_rn(v.x);
        h[1] = __float2half_rn(v.y);
        h[2] = __float2half_rn(v.z);
        h[3] = __float2half_rn(v.w);
        dst[lane + 32 * i] = *(uint2*)h;
    }
    #pragma unroll
    for (int m = 16; m >= 1; m >>= 1)
        s += __shfl_down_sync(0xffffffffu, s, m);
    if (lane == 0) {
        g_norms[w]   = s;
        g_hp_bits[w] = (int)0xFF800000;  // -inf
        g_hn_bits[w] = 0x7F800000;       // +inf
    }
}

// ------------------------- chunk loader -------------------------
// 2 tiles (A, B), 128 rows x 64 fp16 each (128B rows), SW128 swizzled.
__device__ __forceinline__ void load_chunk(int chunk, uint32_t bufBase,
                                           int rowBase, int colBase, int tid) {
    const int k0 = chunk * KCHUNK;
    const __half* srcA = g_xh + (size_t)rowBase * D_SZ;
    const __half* srcB = g_xh + (size_t)colBase * D_SZ;
    #pragma unroll
    for (int i = 0; i < 8; i++) {
        int seg  = tid + i * 256;          // 0..2047
        int c16  = seg & 7;                // 16B segment within row
        int row  = (seg >> 3) & 127;
        int tile = seg >> 10;              // 0 = A, 1 = B
        uint32_t off = (uint32_t)(row * 128 + c16 * 16);
        uint32_t sw  = off ^ ((off >> 3) & 0x70);
        uint32_t dst = bufBase + (uint32_t)tile * TILE_BYTES + sw;
        const __half* base = tile ? srcB : srcA;
        const char* src = (const char*)base + ((size_t)row * D_SZ + k0 + c16 * 8) * 2;
        CP_ASYNC16(dst, src);
    }
    CP_ASYNC_COMMIT();
}

// ------------------------- main tensor-core tile kernel -------------------------
__global__ __launch_bounds__(256, 2) void tile_kernel(float* __restrict__ out) {
    extern __shared__ char dsmem[];
    __shared__ int   labB[BN];
    __shared__ float nrmB[BN];
    __shared__ int   lastFlag;
    __shared__ float redS[8];
    __shared__ int   redC[8];

    // ---- triangular tile decode: blockIdx.x -> (by, bx), bx >= by ----
    const int t = blockIdx.x;
    float ff = (float)(2 * NB + 1);
    int by = (int)((ff - sqrtf(ff * ff - 8.0f * (float)t)) * 0.5f);
    if (by < 0) by = 0;
    if (by > NB - 1) by = NB - 1;
    while (by > 0 && (by * NB - by * (by - 1) / 2) > t) by--;
    while (((by + 1) * NB - (by + 1) * by / 2) <= t) by++;
    const int bx   = by + (t - (by * NB - by * (by - 1) / 2));
    const bool diag = (bx == by);

    const int rowBase = by * BM;
    const int colBase = bx * BN;
    const int tid  = threadIdx.x;
    const int wid  = tid >> 5;
    const int lane = tid & 31;

    uint32_t dynBase = (smem_u32(dsmem) + 1023u) & ~1023u;

    if (tid < BN) {
        labB[tid] = g_labels[colBase + tid];
        nrmB[tid] = g_norms[colBase + tid];
    }

    // ---- prologue loads ----
    load_chunk(0, dynBase, rowBase, colBase, tid);
    load_chunk(1, dynBase + BUF_BYTES, rowBase, colBase, tid);

    // ---- per-thread ldmatrix address parts ----
    const int aRowIn = (lane & 7) + ((lane >> 3) & 1) * 8;
    const int aKH    = ((lane >> 4) & 1) * 16;            // bytes
    const int bNIn = (lane & 7) + ((lane >> 4) & 1) * 8;
    const int bKH  = ((lane >> 3) & 1) * 16;              // bytes

    const int warpRow0 = (wid & 1) * 64;                  // rows within tile
    const int warpCol0 = (wid >> 1) * 32;                 // cols within tile

    uint32_t aOff[4];
    #pragma unroll
    for (int fm = 0; fm < 4; fm++)
        aOff[fm] = (uint32_t)(warpRow0 + fm * 16 + aRowIn) * 128u;
    const uint32_t aMsk = (uint32_t)(aRowIn & 7) << 4;
    uint32_t bOff[2];
    bOff[0] = (uint32_t)(warpCol0 + bNIn) * 128u;
    bOff[1] = (uint32_t)(warpCol0 + 16 + bNIn) * 128u;
    const uint32_t bMsk = (uint32_t)(bNIn & 7) << 4;

    float Cacc[4][4][4];
    #pragma unroll
    for (int i = 0; i < 4; i++)
        #pragma unroll
        for (int j = 0; j < 4; j++)
            #pragma unroll
            for (int k = 0; k < 4; k++) Cacc[i][j][k] = 0.f;

    // ---- pipelined main loop over 8 K-chunks ----
    for (int c = 0; c < NCHUNK; c++) {
        if (c < NCHUNK - 1) { CP_ASYNC_WAIT(1); } else { CP_ASYNC_WAIT(0); }
        __syncthreads();                       // chunk c resident (and labB on c==0)

        const uint32_t bb = dynBase + (uint32_t)(c & 1) * BUF_BYTES;
        const uint32_t sA = bb;
        const uint32_t sB = bb + TILE_BYTES;

        #pragma unroll
        for (int ks = 0; ks < 4; ks++) {
            const uint32_t akb = ((uint32_t)(ks * 32 + aKH)) ^ aMsk;
            const uint32_t bkb = ((uint32_t)(ks * 32 + bKH)) ^ bMsk;
            uint32_t bh[8];
            ldsm_x4(bh,     sB + bOff[0] + bkb);
            ldsm_x4(bh + 4, sB + bOff[1] + bkb);
            #pragma unroll
            for (int fm = 0; fm < 4; fm++) {
                uint32_t a[4];
                ldsm_x4(a, sA + aOff[fm] + akb);
                #pragma unroll
                for (int fn = 0; fn < 4; fn++) mma16816(Cacc[fm][fn], a, bh + fn * 2);
            }
        }

        if (c + 2 < NCHUNK) {
            __syncthreads();                   // all warps done reading this buffer
            load_chunk(c + 2, dynBase + (uint32_t)(c & 1) * BUF_BYTES,
                       rowBase, colBase, tid);
        }
    }

    // ---- epilogue: distances + hardest pos/neg from register fragments ----
    const float NEG_INF = __int_as_float(0xFF800000);
    const float POS_INF = __int_as_float(0x7F800000);
    const int quad = lane >> 2;      // 0..7  (row within 8-row group)
    const int pos  = lane & 3;       // 0..3  (col pair)

    int   laR[8], giR[8];
    float naR[8];
    #pragma unroll
    for (int fm = 0; fm < 4; fm++)
        #pragma unroll
        for (int ar = 0; ar < 2; ar++) {
            int gi = rowBase + warpRow0 + fm * 16 + ar * 8 + quad;
            giR[fm * 2 + ar] = gi;
            laR[fm * 2 + ar] = g_labels[gi];
            naR[fm * 2 + ar] = g_norms[gi];
        }
    int   lbC[8], gjC[8];
    float nbC[8];
    #pragma unroll
    for (int fn = 0; fn < 4; fn++)
        #pragma unroll
        for (int cb = 0; cb < 2; cb++) {
            int cl = warpCol0 + fn * 8 + pos * 2 + cb;
            gjC[fn * 2 + cb] = colBase + cl;
            lbC[fn * 2 + cb] = labB[cl];
            nbC[fn * 2 + cb] = nrmB[cl];
        }

    float hpR[8], hnR[8], hpc[8], hnc[8];
    #pragma unroll
    for (int i = 0; i < 8; i++) { hpR[i] = NEG_INF; hnR[i] = POS_INF; hpc[i] = NEG_INF; hnc[i] = POS_INF; }

    #pragma unroll
    for (int fm = 0; fm < 4; fm++)
        #pragma unroll
        for (int fn = 0; fn < 4; fn++)
            #pragma unroll
            for (int ar = 0; ar < 2; ar++)
                #pragma unroll
                for (int cb = 0; cb < 2; cb++) {
                    int ri = fm * 2 + ar, ci = fn * 2 + cb;
                    float dot = Cacc[fm][fn][ar * 2 + cb];
                    float sq  = fmaxf(fmaf(-2.f, dot, naR[ri] + nbC[ci]), 0.f);
                    float d   = sqrtf(sq);
                    if (laR[ri] == lbC[ci]) {
                        if (giR[ri] != gjC[ci]) {
                            hpR[ri] = fmaxf(hpR[ri], d);
                            hpc[ci] = fmaxf(hpc[ci], d);
                        }
                    } else {
                        hnR[ri] = fminf(hnR[ri], d);
                        hnc[ci] = fminf(hnc[ci], d);
                    }
                }

    // row stats: reduce over the 4 'pos' lanes sharing a row
    #pragma unroll
    for (int i = 0; i < 8; i++) {
        float a = hpR[i], b = hnR[i];
        a = fmaxf(a, __shfl_xor_sync(0xffffffffu, a, 1));
        a = fmaxf(a, __shfl_xor_sync(0xffffffffu, a, 2));
        b = fminf(b, __shfl_xor_sync(0xffffffffu, b, 1));
        b = fminf(b, __shfl_xor_sync(0xffffffffu, b, 2));
        if (pos == 0) {
            atomicMax(&g_hp_bits[giR[i]], __float_as_int(a));
            atomicMin(&g_hn_bits[giR[i]], __float_as_int(b));
        }
    }
    // column stats (symmetry): reduce over the 8 'quad' lanes sharing a column
    if (!diag) {
        #pragma unroll
        for (int i = 0; i < 8; i++) {
            float a = hpc[i], b = hnc[i];
            a = fmaxf(a, __shfl_xor_sync(0xffffffffu, a, 4));
            a = fmaxf(a, __shfl_xor_sync(0xffffffffu, a, 8));
            a = fmaxf(a, __shfl_xor_sync(0xffffffffu, a, 16));
            b = fminf(b, __shfl_xor_sync(0xffffffffu, b, 4));
            b = fminf(b, __shfl_xor_sync(0xffffffffu, b, 8));
            b = fminf(b, __shfl_xor_sync(0xffffffffu, b, 16));
            if (quad == 0) {
                atomicMax(&g_hp_bits[gjC[i]], __float_as_int(a));
                atomicMin(&g_hn_bits[gjC[i]], __float_as_int(b));
            }
        }
    }

    // ---- fused finalize: last CTA reduces hp/hn into the scalar loss ----
    __threadfence();                       // make this CTA's atomics visible
    __syncthreads();                       // all threads' atomics issued
    if (tid == 0) {
        unsigned int prev = atomicAdd(&g_tiles_done, 1u);
        lastFlag = (prev == NTILES - 1u);
    }
    __syncthreads();
    if (!lastFlag) return;

    // this CTA observes all other CTAs' atomics (counter was written after
    // their threadfence; atomicAdd ordering gives acquire semantics here)
    float sum = 0.f;
    int   cnt = 0;
    #pragma unroll
    for (int i = 0; i < B_SZ / 256; i++) {
        int idx = tid + i * 256;
        int hpb = g_hp_bits[idx];
        int hnb = g_hn_bits[idx];
        if (hpb != (int)0xFF800000 && hnb != 0x7F800000) {
            sum += fmaxf(__int_as_float(hpb) - __int_as_float(hnb) + MARGIN_F, 0.f);
            cnt += 1;
        }
    }
    #pragma unroll
    for (int m = 16; m >= 1; m >>= 1) {
        sum += __shfl_xor_sync(0xffffffffu, sum, m);
        cnt += __shfl_xor_sync(0xffffffffu, cnt, m);
    }
    if (lane == 0) { redS[wid] = sum; redC[wid] = cnt; }
    __syncthreads();
    if (wid == 0) {
        float s2 = (lane < 8) ? redS[lane] : 0.f;
        int   c2 = (lane < 8) ? redC[lane] : 0;
        #pragma unroll
        for (int m = 4; m >= 1; m >>= 1) {
            s2 += __shfl_xor_sync(0xffffffffu, s2, m);
            c2 += __shfl_xor_sync(0xffffffffu, c2, m);
        }
        if (lane == 0) out[0] = (c2 > 0) ? (s2 / (float)c2) : 0.f;
    }
}

// ------------------------- launch -------------------------
extern "C" void kernel_launch(void* const* d_in, const int* in_sizes, int n_in,
                              void* d_out, int out_size) {
    const float* X    = (const float*)d_in[0];
    const void*  labp = d_in[1];
    float*       out  = (float*)d_out;

    // idempotent, host-side, not a stream op: safe under graph capture
    cudaFuncSetAttribute(tile_kernel, cudaFuncAttributeMaxDynamicSharedMemorySize, SMEM_DYN);

    prep_kernel<<<B_SZ / 8, 256>>>(X, labp);
    tile_kernel<<<NTILES, 256, SMEM_DYN>>>(out);
}